// round 15
// baseline (speedup 1.0000x reference)
#include <cuda_runtime.h>
#include <cuda_fp16.h>
#include <math.h>

// Problem constants (fixed shapes per reference: N=100000, E=3200000, F_in=54, H=16, F_out=16)
#define MAXN 100000
#define MAXE 3200000
#define F_IN 54
#define F_H  16

#define SCAN_TILE 1024
#define MAX_TILES ((MAXN + SCAN_TILE - 1) / SCAN_TILE)   // 98

// ---------------- scratch (device globals; no allocation allowed) ----------------
__device__ int g_is64;                 // 1 if edge_index buffer is int64, 0 if int32
__device__ int g_deg[MAXN];
__device__ int g_rowptr[MAXN + 1];
__device__ int g_cursor[MAXN];
__device__ int g_col[MAXE];
__device__ int g_dst32[MAXE];
__device__ int g_blocksum[MAX_TILES];
__device__ __align__(32) __half g_hh1[MAXN * F_H];  // layer-1 transformed features (fp16)
__device__ __align__(32) __half g_hh2[MAXN * F_H];  // layer-2 transformed features (fp16)
__device__ float g_ad1[MAXN];
__device__ float g_ad2[MAXN];

// ---------------- zero + dtype sniff (merged) ----------------
__global__ void k_zero_sniff(const int* __restrict__ ei_raw, int n) {
    int i = blockIdx.x * blockDim.x + threadIdx.x;
    if (i < n) g_deg[i] = 0;
    if (i == 0) {
        int all_hi_zero = 1;
        for (int j = 0; j < 32; j++) {
            if (ei_raw[2 * j + 1] != 0) { all_hi_zero = 0; break; }
        }
        g_is64 = all_hi_zero;
    }
}

__device__ __forceinline__ int edge_at(const void* __restrict__ ei, size_t idx) {
    if (g_is64) return (int)((const long long*)ei)[idx];
    return ((const int*)ei)[idx];
}

// ---------------- CSR build ----------------
__global__ void k_hist(const void* __restrict__ ei, int e, int n) {
    int i = blockIdx.x * blockDim.x + threadIdx.x;
    if (i < e) {
        int d = edge_at(ei, (size_t)e + i);
        g_dst32[i] = d;
        if ((unsigned)d < (unsigned)n) atomicAdd(&g_deg[d], 1);
    }
}

__global__ __launch_bounds__(256) void k_scan_reduce(int n) {
    __shared__ int sh[256];
    int t = threadIdx.x;
    int base = blockIdx.x * SCAN_TILE + t * 4;
    int s = 0;
    if (base + 3 < n) {
        int4 v = *(const int4*)&g_deg[base];
        s = v.x + v.y + v.z + v.w;
    } else {
        for (int j = 0; j < 4; j++) if (base + j < n) s += g_deg[base + j];
    }
    sh[t] = s;
    __syncthreads();
    for (int off = 128; off > 0; off >>= 1) {
        if (t < off) sh[t] += sh[t + off];
        __syncthreads();
    }
    if (t == 0) g_blocksum[blockIdx.x] = sh[0];
}

// Fused: each block locally scans the (<=98) tile sums, then scans its own tile.
__global__ __launch_bounds__(256) void k_scan_final(int ntiles, int n) {
    __shared__ int ts[128];
    __shared__ int sh[256];
    int t = threadIdx.x;
    if (t < 128) ts[t] = (t < ntiles) ? g_blocksum[t] : 0;
    __syncthreads();
    for (int off = 1; off < 128; off <<= 1) {
        int x = (t < 128) ? ts[t] : 0;
        int add = (t >= off && t < 128) ? ts[t - off] : 0;
        __syncthreads();
        if (t < 128) ts[t] = x + add;
        __syncthreads();
    }
    int blockoff = (blockIdx.x == 0) ? 0 : ts[blockIdx.x - 1];
    if (blockIdx.x == 0 && t == 0) g_rowptr[n] = ts[ntiles - 1];

    int base = blockIdx.x * SCAN_TILE + t * 4;
    int v0 = 0, v1 = 0, v2 = 0, v3 = 0;
    if (base + 3 < n) {
        int4 v = *(const int4*)&g_deg[base];
        v0 = v.x; v1 = v.y; v2 = v.z; v3 = v.w;
    } else {
        if (base + 0 < n) v0 = g_deg[base + 0];
        if (base + 1 < n) v1 = g_deg[base + 1];
        if (base + 2 < n) v2 = g_deg[base + 2];
        if (base + 3 < n) v3 = g_deg[base + 3];
    }
    int local = v0 + v1 + v2 + v3;
    sh[t] = local;
    __syncthreads();
    for (int off = 1; off < 256; off <<= 1) {
        int x = sh[t];
        int add = (t >= off) ? sh[t - off] : 0;
        __syncthreads();
        sh[t] = x + add;
        __syncthreads();
    }
    int run = blockoff + sh[t] - local;
    int r0 = run, r1 = run + v0, r2 = r1 + v1, r3 = r2 + v2;
    if (base + 3 < n) {
        int4 w = make_int4(r0, r1, r2, r3);
        *(int4*)&g_rowptr[base] = w;
        *(int4*)&g_cursor[base] = w;
    } else {
        if (base + 0 < n) { g_rowptr[base + 0] = r0; g_cursor[base + 0] = r0; }
        if (base + 1 < n) { g_rowptr[base + 1] = r1; g_cursor[base + 1] = r1; }
        if (base + 2 < n) { g_rowptr[base + 2] = r2; g_cursor[base + 2] = r2; }
        if (base + 3 < n) { g_rowptr[base + 3] = r3; g_cursor[base + 3] = r3; }
    }
}

__global__ void k_scatter(const void* __restrict__ ei, int e, int n) {
    int i = blockIdx.x * blockDim.x + threadIdx.x;
    if (i < e) {
        int s = edge_at(ei, (size_t)i);
        int d = g_dst32[i];
        if ((unsigned)d < (unsigned)n && (unsigned)s < (unsigned)n) {
            int pos = atomicAdd(&g_cursor[d], 1);
            g_col[pos] = s;
        }
    }
}

// ---------------- node transform, layer 1: h1 = x @ W1 (fp16 store); a1_dst dot fp32 ----------------
__global__ __launch_bounds__(128) void k_node1(const float* __restrict__ x,
                                               const float* __restrict__ W,
                                               const float* __restrict__ adst,
                                               int n) {
    __shared__ float sw[F_IN * F_H];
    __shared__ float sx[128 * F_IN];
    int tid = threadIdx.x;
    for (int i = tid; i < F_IN * F_H; i += 128) sw[i] = W[i];
    int base = blockIdx.x * 128;
    int cnt = min(128, n - base);
    if (cnt <= 0) return;
    for (int i = tid; i < cnt * F_IN; i += 128) sx[i] = x[(size_t)base * F_IN + i];
    __syncthreads();
    if (tid >= cnt) return;
    int node = base + tid;
    float acc[F_H];
#pragma unroll
    for (int k = 0; k < F_H; k++) acc[k] = 0.f;
    for (int j = 0; j < F_IN; j++) {
        float xv = sx[tid * F_IN + j];
#pragma unroll
        for (int k = 0; k < F_H; k++) acc[k] = fmaf(xv, sw[j * F_H + k], acc[k]);
    }
    float dd = 0.f;
#pragma unroll
    for (int k = 0; k < F_H; k++) dd = fmaf(acc[k], __ldg(&adst[k]), dd);
    g_ad1[node] = dd;
    unsigned u[8];
#pragma unroll
    for (int k = 0; k < 8; k++) {
        __half2 p = __floats2half2_rn(acc[2 * k], acc[2 * k + 1]);
        u[k] = *(unsigned*)&p;
    }
    uint4* hp = (uint4*)&g_hh1[(size_t)node * F_H];
    hp[0] = make_uint4(u[0], u[1], u[2], u[3]);
    hp[1] = make_uint4(u[4], u[5], u[6], u[7]);
}

__device__ __forceinline__ float leaky(float v) { return v > 0.f ? v : 0.2f * v; }

// unpack 2 uint4 (16 half) into f[16]
__device__ __forceinline__ void unp_row(const uint4& A, const uint4& B, float* f) {
    float2 t2;
#define UNP2(word, k0) { __half2 _h = *(__half2*)&(word); t2 = __half22float2(_h); f[k0] = t2.x; f[k0+1] = t2.y; }
    UNP2(A.x, 0)  UNP2(A.y, 2)  UNP2(A.z, 4)  UNP2(A.w, 6)
    UNP2(B.x, 8)  UNP2(B.y, 10) UNP2(B.z, 12) UNP2(B.w, 14)
#undef UNP2
}

// ---------------- edge aggregation: 8-lane group per dst node, single-pass softmax ----------------
// Batch-of-4 software pipeline: 4 col indices prefetched, then 8 independent
// LDG.128 row loads in flight before any unpack (raises per-thread MLP ~4x;
// the kernel is L2-latency-bound, not bandwidth-bound).
#define GRP 8
template <int LAYER1>
__global__ __launch_bounds__(128) void k_edge(const float* __restrict__ bias,
                                              const float* __restrict__ asrc,
                                              const float* __restrict__ W2,
                                              const float* __restrict__ a2d,
                                              float* __restrict__ outp,
                                              int n) {
    __shared__ float sw2[F_H * F_H];
    __shared__ float sa[F_H], sd2[F_H], sb[F_H];
    int tid = threadIdx.x;
    if (LAYER1) {
        for (int i = tid; i < F_H * F_H; i += 128) sw2[i] = W2[i];
    }
    if (tid < F_H) {
        sb[tid] = bias[tid];
        sa[tid] = asrc[tid];
        if (LAYER1) sd2[tid] = a2d[tid];
    }
    __syncthreads();

    int gid = (blockIdx.x * blockDim.x + tid) / GRP;   // node
    int sub = tid & (GRP - 1);
    if (gid >= n) return;

    const __half* __restrict__ hh = LAYER1 ? g_hh1 : g_hh2;
    float adv = LAYER1 ? g_ad1[gid] : g_ad2[gid];
    int beg = g_rowptr[gid];
    int end = g_rowptr[gid + 1];

    float acc[F_H];
#pragma unroll
    for (int k = 0; k < F_H; k++) acc[k] = 0.f;
    float den = 0.f;

    for (int i0 = beg + sub; i0 < end; i0 += 4 * GRP) {
        int i1 = i0 + GRP, i2 = i0 + 2 * GRP, i3 = i0 + 3 * GRP;
        bool v1 = i1 < end, v2 = i2 < end, v3 = i3 < end;
        // prefetch col indices (independent loads; invalid slots alias edge 0 -> L1 hit)
        int s0 = __ldg(&g_col[i0]);
        int s1 = v1 ? __ldg(&g_col[i1]) : s0;
        int s2 = v2 ? __ldg(&g_col[i2]) : s0;
        int s3 = v3 ? __ldg(&g_col[i3]) : s0;
        // issue all 8 row loads before any unpack (MLP=8)
        const uint4* p0 = (const uint4*)(hh + (size_t)s0 * F_H);
        const uint4* p1 = (const uint4*)(hh + (size_t)s1 * F_H);
        const uint4* p2 = (const uint4*)(hh + (size_t)s2 * F_H);
        const uint4* p3 = (const uint4*)(hh + (size_t)s3 * F_H);
        uint4 A0 = __ldg(p0), B0 = __ldg(p0 + 1);
        uint4 A1 = __ldg(p1), B1 = __ldg(p1 + 1);
        uint4 A2 = __ldg(p2), B2 = __ldg(p2 + 1);
        uint4 A3 = __ldg(p3), B3 = __ldg(p3 + 1);

        float f[F_H];
#define PROC(Ak, Bk, valid)  { \
        unp_row(Ak, Bk, f); \
        float as = 0.f; \
        _Pragma("unroll") for (int k = 0; k < F_H; k++) as = fmaf(f[k], sa[k], as); \
        float wt = (valid) ? __expf(leaky(as + adv)) : 0.f; \
        den += wt; \
        _Pragma("unroll") for (int k = 0; k < F_H; k++) acc[k] = fmaf(wt, f[k], acc[k]); }

        PROC(A0, B0, true)
        PROC(A1, B1, v1)
        PROC(A2, B2, v2)
        PROC(A3, B3, v3)
#undef PROC
    }

    // 8-lane butterfly: afterwards ALL lanes hold the full sums
#pragma unroll
    for (int o = GRP / 2; o; o >>= 1) {
        den += __shfl_xor_sync(0xffffffffu, den, o, GRP);
#pragma unroll
        for (int k = 0; k < F_H; k++)
            acc[k] += __shfl_xor_sync(0xffffffffu, acc[k], o, GRP);
    }

    // self-loop (lane-uniform within group)
    float hs[F_H];
    {
        const uint4* hp = (const uint4*)(hh + (size_t)gid * F_H);
        uint4 A = __ldg(hp), B = __ldg(hp + 1);
        unp_row(A, B, hs);
    }
    float as_self = 0.f;
#pragma unroll
    for (int k = 0; k < F_H; k++) as_self = fmaf(hs[k], sa[k], as_self);
    float ws = __expf(leaky(as_self + adv));
    den += ws;
    float inv = 1.0f / den;

    if (LAYER1) {
        // g1 = elu(aggregate + b1), computed redundantly on all 8 lanes
        float g1v[F_H];
#pragma unroll
        for (int k = 0; k < F_H; k++) {
            float v = (acc[k] + ws * hs[k]) * inv + sb[k];
            g1v[k] = v > 0.f ? v : expm1f(v);
        }
        // each lane: 2 columns of h2 = g1 @ W2
        int k0 = 2 * sub, k1 = 2 * sub + 1;
        float o0 = 0.f, o1 = 0.f;
#pragma unroll
        for (int j = 0; j < F_H; j++) {
            o0 = fmaf(g1v[j], sw2[j * F_H + k0], o0);
            o1 = fmaf(g1v[j], sw2[j * F_H + k1], o1);
        }
        // partial a2_dst dot, reduce over group
        float pd = o0 * sd2[k0] + o1 * sd2[k1];
#pragma unroll
        for (int o = GRP / 2; o; o >>= 1)
            pd += __shfl_xor_sync(0xffffffffu, pd, o, GRP);
        __half2 p = __floats2half2_rn(o0, o1);
        ((unsigned*)g_hh2)[(size_t)gid * 8 + sub] = *(unsigned*)&p;
        if (sub == 0) g_ad2[gid] = pd;
    } else {
        // final output: each lane writes its 2 features
        int k0 = 2 * sub;
        float v0 = (acc[k0] + ws * hs[k0]) * inv + sb[k0];
        float v1 = (acc[k0 + 1] + ws * hs[k0 + 1]) * inv + sb[k0 + 1];
        ((float2*)outp)[(size_t)gid * 8 + sub] = make_float2(v0, v1);
    }
}

// ---------------- launch ----------------
extern "C" void kernel_launch(void* const* d_in, const int* in_sizes, int n_in,
                              void* d_out, int out_size) {
    const float* x   = (const float*)d_in[0];
    const void*  ei  = d_in[1];                    // int32 or int64 — sniffed on device
    const float* W1  = (const float*)d_in[2];
    const float* a1s = (const float*)d_in[3];
    const float* a1d = (const float*)d_in[4];
    const float* b1  = (const float*)d_in[5];
    const float* W2  = (const float*)d_in[6];
    const float* a2s = (const float*)d_in[7];
    const float* a2d = (const float*)d_in[8];
    const float* b2  = (const float*)d_in[9];
    float* out = (float*)d_out;

    int n = in_sizes[0] / F_IN;     // 100000
    int e = in_sizes[1] / 2;        // 3200000 (elements/2 regardless of int width)
    if (n > MAXN) n = MAXN;
    if (e > MAXE) e = MAXE;
    int ntiles = (n + SCAN_TILE - 1) / SCAN_TILE;

    // CSR build (once, reused by both layers)
    k_zero_sniff<<<(n + 255) / 256, 256>>>((const int*)ei, n);
    k_hist<<<(e + 255) / 256, 256>>>(ei, e, n);
    k_scan_reduce<<<ntiles, 256>>>(n);
    k_scan_final<<<ntiles, 256>>>(ntiles, n);
    k_scatter<<<(e + 255) / 256, 256>>>(ei, e, n);

    // Layer 1 node transform
    k_node1<<<(n + 127) / 128, 128>>>(x, W1, a1d, n);

    // Layer 1 edge aggregation + fused layer-2 node transform
    long long threads = (long long)n * GRP;
    unsigned blocks = (unsigned)((threads + 127) / 128);
    k_edge<1><<<blocks, 128>>>(b1, a1s, W2, a2d, nullptr, n);

    // Layer 2 edge aggregation -> final output
    k_edge<0><<<blocks, 128>>>(b2, a2s, nullptr, nullptr, out, n);
}